// round 16
// baseline (speedup 1.0000x reference)
#include <cuda_runtime.h>
#include <cuda_fp16.h>
#include <cuda_bf16.h>

// ---------------- problem constants ----------------
#define B      512
#define C1     64
#define C2     128
#define FLAT   2048
#define F1     512
#define F2     10
#define BN_EPS 1e-5f

// ---------------- device scratch ----------------
__device__ unsigned g_maxabs[4];                  // slots 1..3; zero-init; atomicMax idempotent
__device__ __half g_qw2h[25 * C2 * C1];           // conv2 ternary [khkw][oc][ci]
__device__ __half g_qf1h[F1 * FLAT];              // fc1 ternary [f][k]
__device__ float  g_qf2[F2 * F1];
__device__ float g_pool1[B * 144 * C1];           // RAW pooled conv1 (pre-BN), [b][pixel][ci]
__device__ float g_p1sum[C1 * B], g_p1sq[C1 * B];
__device__ float g_scale1[C1], g_shift1[C1];
__device__ float g_p2sum[C2 * B], g_p2sq[C2 * B];
__device__ float g_scale2[C2], g_shift2[C2];
__device__ float g_h1[B * FLAT];                  // RAW pooled conv2 (pre-BN)
__device__ float g_fc1[B * F1];                   // RAW fc1 (pre-BN)
__device__ float g_p3s[F1 * 32], g_p3q[F1 * 32];  // BN3 partials: [feature][b-tile of 16]

// ---------------- asm helpers ----------------
__device__ __forceinline__ void cp16(__half* smem_dst, const __half* gsrc) {
    unsigned s = (unsigned)__cvta_generic_to_shared(smem_dst);
    asm volatile("cp.async.cg.shared.global [%0], [%1], 16;\n" :: "r"(s), "l"(gsrc));
}
#define CP_COMMIT() asm volatile("cp.async.commit_group;\n" ::: "memory")
#define CP_WAIT0()  asm volatile("cp.async.wait_group 0;\n" ::: "memory")

__device__ __forceinline__ void ldsm4(unsigned& r0, unsigned& r1, unsigned& r2, unsigned& r3,
                                      unsigned saddr) {
    asm volatile("ldmatrix.sync.aligned.m8n8.x4.shared.b16 {%0,%1,%2,%3}, [%4];"
                 : "=r"(r0), "=r"(r1), "=r"(r2), "=r"(r3) : "r"(saddr));
}
__device__ __forceinline__ void ldsm2(unsigned& r0, unsigned& r1, unsigned saddr) {
    asm volatile("ldmatrix.sync.aligned.m8n8.x2.shared.b16 {%0,%1}, [%2];"
                 : "=r"(r0), "=r"(r1) : "r"(saddr));
}

// ---------------- quantization (slots 1..3: conv2, fc1, fc2 weights) ----------------
__global__ void k_absmax_all(const float* __restrict__ w1, const float* __restrict__ w2,
                             const float* __restrict__ w3) {
    cudaTriggerProgrammaticLaunchCompletion();
    const int slot = blockIdx.y + 1;
    const float* w = (slot == 1) ? w1 : (slot == 2) ? w2 : w3;
    const int n4 = ((slot == 1) ? 204800 : (slot == 2) ? 1048576 : 5120) >> 2;
    const float4* w4 = (const float4*)w;
    unsigned m = 0u;
    #pragma unroll 4
    for (int i = blockIdx.x * blockDim.x + threadIdx.x; i < n4; i += gridDim.x * blockDim.x) {
        float4 v = w4[i];
        m = max(m, __float_as_uint(fabsf(v.x)));
        m = max(m, __float_as_uint(fabsf(v.y)));
        m = max(m, __float_as_uint(fabsf(v.z)));
        m = max(m, __float_as_uint(fabsf(v.w)));
    }
    #pragma unroll
    for (int o = 16; o; o >>= 1)
        m = max(m, __shfl_xor_sync(0xffffffffu, m, o));
    if ((threadIdx.x & 31) == 0) atomicMax(&g_maxabs[slot], m);
}

__global__ void k_quant_all(const float* __restrict__ w1,
                            const float* __restrict__ w2, const float* __restrict__ w3) {
    cudaTriggerProgrammaticLaunchCompletion();   // conv1 is self-contained: safe to cascade
    cudaGridDependencySynchronize();             // need g_maxabs from absmax
    const int slot = blockIdx.y + 1;
    const float* w = (slot == 1) ? w1 : (slot == 2) ? w2 : w3;
    const int n4 = ((slot == 1) ? 204800 : (slot == 2) ? 1048576 : 5120) >> 2;
    const float4* w4 = (const float4*)w;
    const float t = 0.05f * __uint_as_float(g_maxabs[slot]);
    #pragma unroll 2
    for (int i = blockIdx.x * blockDim.x + threadIdx.x; i < n4; i += gridDim.x * blockDim.x) {
        float4 v = w4[i];
        float q0 = (v.x > t) ? 1.0f : ((v.x < -t) ? -1.0f : 0.0f);
        float q1 = (v.y > t) ? 1.0f : ((v.y < -t) ? -1.0f : 0.0f);
        float q2 = (v.z > t) ? 1.0f : ((v.z < -t) ? -1.0f : 0.0f);
        float q3 = (v.w > t) ? 1.0f : ((v.w < -t) ? -1.0f : 0.0f);
        int base = 4 * i;
        if (slot == 1) {
            float qs[4] = {q0, q1, q2, q3};
            #pragma unroll
            for (int u = 0; u < 4; u++) {
                int idx = base + u;
                int oc = idx / 1600, rem = idx - oc * 1600, ci = rem / 25, kk = rem - ci * 25;
                g_qw2h[kk * (C2 * C1) + oc * C1 + ci] = __float2half(qs[u]);
            }
        } else if (slot == 2) {
            *(__half2*)&g_qf1h[base]     = __floats2half2_rn(q0, q1);
            *(__half2*)&g_qf1h[base + 2] = __floats2half2_rn(q2, q3);
        } else {
            *(float4*)&g_qf2[base] = make_float4(q0, q1, q2, q3);
        }
    }
}

// ---------------- conv1: fp16 mma; fully self-contained (own absmax + quant) ------------
#define CV1_SMEM_BYTES (3136 + 5120 + 46080)
__global__ __launch_bounds__(256) void k_conv1(const float* __restrict__ x,
                                               const float* __restrict__ w1raw) {
    cudaTriggerProgrammaticLaunchCompletion();
    extern __shared__ char c1sm[];
    float*  sxf = (float*)c1sm;
    __half* sA  = (__half*)(c1sm + 3136);
    __half* sB  = (__half*)(c1sm + 3136 + 5120);
    __shared__ float srs[64][9], srq[64][9];
    __shared__ unsigned swm[8];
    const int b = blockIdx.x, t = threadIdx.x;
    const int lane = t & 31, warp = t >> 5;
    const int l4 = lane >> 2, lm4 = lane & 3;

    for (int i = t; i < 784; i += 256) sxf[i] = x[b * 784 + i];
    {
        unsigned mm = 0u;
        for (int i = t; i < 1600; i += 256) mm = max(mm, __float_as_uint(fabsf(w1raw[i])));
        #pragma unroll
        for (int o = 16; o; o >>= 1) mm = max(mm, __shfl_xor_sync(0xffffffffu, mm, o));
        if (lane == 0) swm[warp] = mm;
    }
    __syncthreads();
    {
        unsigned m8 = swm[0];
        #pragma unroll
        for (int j = 1; j < 8; j++) m8 = max(m8, swm[j]);
        const float tq = 0.05f * __uint_as_float(m8);
        for (int i = t; i < 1600; i += 256) {
            int oc = i / 25, k = i - oc * 25;
            float v = w1raw[i];
            sA[oc * 40 + k] = __float2half((v > tq) ? 1.0f : ((v < -tq) ? -1.0f : 0.0f));
        }
        for (int i = t; i < 64 * 7; i += 256) {
            int oc = i / 7, k = 25 + i % 7;
            sA[oc * 40 + k] = __ushort_as_half((unsigned short)0);
        }
    }
    {
        const int kp = t & 15, n0 = t >> 4;
        const int k0 = 2 * kp;
        const int kh0 = k0 / 5, kw0 = k0 - 5 * kh0;
        const int kh1 = (k0 + 1) / 5, kw1 = (k0 + 1) - 5 * kh1;
        const bool e0 = (k0 < 25), e1 = (k0 + 1 < 25);
        #pragma unroll 4
        for (int st = 0; st < 36; st++) {
            int n = n0 + 16 * st;
            int w = n >> 2, j = n & 3;
            int py = w / 12, px = w - 12 * py;
            int iy = 2 * py + (j >> 1), ix = 2 * px + (j & 1);
            float v0 = e0 ? sxf[(iy + kh0) * 28 + ix + kw0] : 0.f;
            float v1 = e1 ? sxf[(iy + kh1) * 28 + ix + kw1] : 0.f;
            *(__half2*)&sB[n * 40 + k0] = __floats2half2_rn(v0, v1);
        }
    }
    __syncthreads();

    unsigned a[4][2][4];
    #pragma unroll
    for (int mt = 0; mt < 4; mt++) {
        const __half* ap = sA + (mt * 16 + l4) * 40 + 2 * lm4;
        #pragma unroll
        for (int ks = 0; ks < 2; ks++) {
            a[mt][ks][0] = *(const unsigned*)(ap + 16 * ks);
            a[mt][ks][1] = *(const unsigned*)(ap + 16 * ks + 8 * 40);
            a[mt][ks][2] = *(const unsigned*)(ap + 16 * ks + 8);
            a[mt][ks][3] = *(const unsigned*)(ap + 16 * ks + 8 * 40 + 8);
        }
    }

    float s0a[4] = {0,0,0,0}, s1a[4] = {0,0,0,0};
    float q0a[4] = {0,0,0,0}, q1a[4] = {0,0,0,0};

    #pragma unroll
    for (int nt = 0; nt < 9; nt++) {
        const __half* bp = sB + (warp * 72 + nt * 8 + l4) * 40 + 2 * lm4;
        unsigned bf[2][2];
        #pragma unroll
        for (int ks = 0; ks < 2; ks++) {
            bf[ks][0] = *(const unsigned*)(bp + 16 * ks);
            bf[ks][1] = *(const unsigned*)(bp + 16 * ks + 8);
        }
        float c[4][4];
        #pragma unroll
        for (int mt = 0; mt < 4; mt++) {
            c[mt][0] = c[mt][1] = c[mt][2] = c[mt][3] = 0.f;
            #pragma unroll
            for (int ks = 0; ks < 2; ks++)
                asm volatile(
                    "mma.sync.aligned.m16n8k16.row.col.f32.f16.f16.f32 "
                    "{%0,%1,%2,%3},{%4,%5,%6,%7},{%8,%9},{%0,%1,%2,%3};"
                    : "+f"(c[mt][0]), "+f"(c[mt][1]), "+f"(c[mt][2]), "+f"(c[mt][3])
                    : "r"(a[mt][ks][0]), "r"(a[mt][ks][1]), "r"(a[mt][ks][2]), "r"(a[mt][ks][3]),
                      "r"(bf[ks][0]), "r"(bf[ks][1]));
        }
        const int wdw = warp * 18 + nt * 2 + (lm4 >> 1);
        #pragma unroll
        for (int mt = 0; mt < 4; mt++) {
            s0a[mt] += c[mt][0] + c[mt][1];
            q0a[mt] += c[mt][0]*c[mt][0] + c[mt][1]*c[mt][1];
            s1a[mt] += c[mt][2] + c[mt][3];
            q1a[mt] += c[mt][2]*c[mt][2] + c[mt][3]*c[mt][3];
            float m0 = fmaxf(c[mt][0], c[mt][1]);
            float m1 = fmaxf(c[mt][2], c[mt][3]);
            m0 = fmaxf(m0, __shfl_xor_sync(0xffffffffu, m0, 1));
            m1 = fmaxf(m1, __shfl_xor_sync(0xffffffffu, m1, 1));
            if ((lm4 & 1) == 0) {
                int oc = mt * 16 + l4;
                g_pool1[b * 9216 + wdw * 64 + oc]     = m0;
                g_pool1[b * 9216 + wdw * 64 + oc + 8] = m1;
            }
        }
    }

    #pragma unroll
    for (int mt = 0; mt < 4; mt++) {
        float s0 = s0a[mt], q0 = q0a[mt], s1 = s1a[mt], q1 = q1a[mt];
        s0 += __shfl_xor_sync(0xffffffffu, s0, 1); s0 += __shfl_xor_sync(0xffffffffu, s0, 2);
        q0 += __shfl_xor_sync(0xffffffffu, q0, 1); q0 += __shfl_xor_sync(0xffffffffu, q0, 2);
        s1 += __shfl_xor_sync(0xffffffffu, s1, 1); s1 += __shfl_xor_sync(0xffffffffu, s1, 2);
        q1 += __shfl_xor_sync(0xffffffffu, q1, 1); q1 += __shfl_xor_sync(0xffffffffu, q1, 2);
        if (lm4 == 0) {
            srs[mt * 16 + l4][warp] = s0;     srq[mt * 16 + l4][warp] = q0;
            srs[mt * 16 + l4 + 8][warp] = s1; srq[mt * 16 + l4 + 8][warp] = q1;
        }
    }
    __syncthreads();
    if (t < 64) {
        float S = 0.f, Q = 0.f;
        #pragma unroll
        for (int w = 0; w < 8; w++) { S += srs[t][w]; Q += srq[t][w]; }
        g_p1sum[t * B + b] = S;
        g_p1sq [t * B + b] = Q;
    }
}

// ---------------- BN finalize: one 32-thread block per channel ----------------
__global__ void k_bnfin1(const float* __restrict__ gamma, const float* __restrict__ beta) {
    cudaGridDependencySynchronize();
    cudaTriggerProgrammaticLaunchCompletion();   // gate: conv2 may launch now
    const int lane = threadIdx.x & 31;
    const int c = blockIdx.x;
    const float4* ps = (const float4*)&g_p1sum[c * B];
    const float4* pq = (const float4*)&g_p1sq [c * B];
    float s = 0.f, q = 0.f;
    #pragma unroll
    for (int i = 0; i < 4; i++) {
        float4 v = ps[lane * 4 + i]; s += v.x + v.y + v.z + v.w;
        float4 u = pq[lane * 4 + i]; q += u.x + u.y + u.z + u.w;
    }
    #pragma unroll
    for (int o = 16; o; o >>= 1) {
        s += __shfl_xor_sync(0xffffffffu, s, o);
        q += __shfl_xor_sync(0xffffffffu, q, o);
    }
    if (lane == 0) {
        const float invN = 1.0f / (float)(B * 576);
        float mean = s * invN;
        float var  = q * invN - mean * mean;
        float sc = gamma[c] * rsqrtf(var + BN_EPS);
        g_scale1[c] = sc;
        g_shift1[c] = beta[c] - mean * sc;
    }
}

__global__ void k_bnfin2(const float* __restrict__ gamma, const float* __restrict__ beta) {
    cudaGridDependencySynchronize();
    cudaTriggerProgrammaticLaunchCompletion();   // gate: fc1 may launch now
    const int lane = threadIdx.x & 31;
    const int c = blockIdx.x;
    const float4* ps = (const float4*)&g_p2sum[c * B];
    const float4* pq = (const float4*)&g_p2sq [c * B];
    float s = 0.f, q = 0.f;
    #pragma unroll
    for (int i = 0; i < 4; i++) {
        float4 v = ps[lane * 4 + i]; s += v.x + v.y + v.z + v.w;
        float4 u = pq[lane * 4 + i]; q += u.x + u.y + u.z + u.w;
    }
    #pragma unroll
    for (int o = 16; o; o >>= 1) {
        s += __shfl_xor_sync(0xffffffffu, s, o);
        q += __shfl_xor_sync(0xffffffffu, q, o);
    }
    if (lane == 0) {
        const float invN = 1.0f / (float)(B * 64);
        float mean = s * invN;
        float var  = q * invN - mean * mean;
        float sc = gamma[c] * rsqrtf(var + BN_EPS);
        g_scale2[c] = sc;
        g_shift2[c] = beta[c] - mean * sc;
    }
}

// ---------------- conv2: fp16 mma + ldmatrix frags, 2 images/block, 2 blocks/SM ---------
#define CV2_CSTR 72
#define CV2_IMGH (144 * CV2_CSTR)
#define CV2_SX_H (2 * CV2_IMGH)
#define CV2_WBUF (C2 * CV2_CSTR)
#define CV2_SMEM_BYTES ((CV2_SX_H + 2 * CV2_WBUF) * 2)

__global__ __launch_bounds__(256, 2) void k_conv2() {
    cudaTriggerProgrammaticLaunchCompletion();
    extern __shared__ __half smh[];
    __half* sxh = smh;
    __half* sA0 = smh + CV2_SX_H;
    __half* sA1 = sA0 + CV2_WBUF;
    const int b2 = blockIdx.x * 2;
    const int t = threadIdx.x;
    const int lane = t & 31, warp = t >> 5;
    const int l4 = lane >> 2, lm4 = lane & 3;
    const int wm = warp >> 2, wn = warp & 3;
    const int img = wn >> 1, yh = wn & 1;
    const int m0w = wm * 64;

    {   // weights provably complete (launched after bnfin1's post-sync trigger)
        const __half* wsrc = g_qw2h;
        #pragma unroll
        for (int j = 0; j < 4; j++) {
            int idx = t + 256 * j;
            int oc = idx >> 3, c8 = idx & 7;
            cp16(sA0 + oc * CV2_CSTR + c8 * 8, wsrc + idx * 8);
        }
        CP_COMMIT();
    }

    cudaGridDependencySynchronize();             // need scale1/shift1 from bnfin1

    for (int idx = t; idx < 2 * 144 * 32; idx += 256) {
        int im = idx / 4608, r = idx - im * 4608;
        int p = r >> 5, cp = r & 31;
        int ci0 = 2 * cp;
        float2 v = *(const float2*)&g_pool1[(b2 + im) * 9216 + p * 64 + ci0];
        float v0 = fmaxf(fmaf(g_scale1[ci0],     v.x, g_shift1[ci0]),     0.0f);
        float v1 = fmaxf(fmaf(g_scale1[ci0 + 1], v.y, g_shift1[ci0 + 1]), 0.0f);
        *(__half2*)&sxh[im * CV2_IMGH + p * CV2_CSTR + ci0] = __floats2half2_rn(v0, v1);
    }

    float c[4][4][4];
    #pragma unroll
    for (int i = 0; i < 4; i++)
        #pragma unroll
        for (int j = 0; j < 4; j++)
            #pragma unroll
            for (int r = 0; r < 4; r++) c[i][j][r] = 0.f;

    const unsigned sxa  = (unsigned)__cvta_generic_to_shared(sxh);
    const unsigned sA0a = (unsigned)__cvta_generic_to_shared(sA0);
    const unsigned sA1a = (unsigned)__cvta_generic_to_shared(sA1);
    const unsigned aoff = (unsigned)((m0w + (lane & 15)) * CV2_CSTR) * 2u + (((unsigned)lane >> 4) << 4);
    const unsigned bln  = (unsigned)((lane & 7) * CV2_CSTR) * 2u + ((((unsigned)lane >> 3) & 1u) << 4);

    for (int khkw = 0; khkw < 25; khkw++) {
        const unsigned sAa = (khkw & 1) ? sA1a : sA0a;
        CP_WAIT0();
        __syncthreads();
        if (khkw < 24) {
            __half* dst = (khkw & 1) ? sA0 : sA1;
            const __half* wsrc = g_qw2h + (khkw + 1) * (C2 * C1);
            #pragma unroll
            for (int j = 0; j < 4; j++) {
                int idx = t + 256 * j;
                int oc = idx >> 3, c8 = idx & 7;
                cp16(dst + oc * CV2_CSTR + c8 * 8, wsrc + idx * 8);
            }
            CP_COMMIT();
        }
        const int kh = khkw / 5, kw = khkw - 5 * kh;
        const unsigned bbase = sxa
            + (unsigned)(img * CV2_IMGH + ((yh * 4 + kh) * 12 + kw) * CV2_CSTR) * 2u + bln;
        #pragma unroll
        for (int ks = 0; ks < 4; ks++) {
            const unsigned k0b = (unsigned)(ks * 32);
            unsigned a[4][4], bf[4][2];
            #pragma unroll
            for (int mt = 0; mt < 4; mt++)
                ldsm4(a[mt][0], a[mt][1], a[mt][2], a[mt][3],
                      sAa + aoff + (unsigned)(mt * 16 * CV2_CSTR * 2) + k0b);
            #pragma unroll
            for (int nt = 0; nt < 4; nt++)
                ldsm2(bf[nt][0], bf[nt][1],
                      bbase + (unsigned)(nt * 12 * CV2_CSTR * 2) + k0b);
            #pragma unroll
            for (int mt = 0; mt < 4; mt++)
                #pragma unroll
                for (int nt = 0; nt < 4; nt++)
                    asm volatile(
                        "mma.sync.aligned.m16n8k16.row.col.f32.f16.f16.f32 "
                        "{%0,%1,%2,%3},{%4,%5,%6,%7},{%8,%9},{%0,%1,%2,%3};"
                        : "+f"(c[mt][nt][0]), "+f"(c[mt][nt][1]),
                          "+f"(c[mt][nt][2]), "+f"(c[mt][nt][3])
                        : "r"(a[mt][0]), "r"(a[mt][1]), "r"(a[mt][2]), "r"(a[mt][3]),
                          "r"(bf[nt][0]), "r"(bf[nt][1]));
        }
    }

    __syncthreads();
    float* sps = (float*)sA0;
    float* spq = sps + 512;
    const int bimg = b2 + img;
    #pragma unroll
    for (int mt = 0; mt < 4; mt++) {
        int r0 = m0w + mt * 16 + l4;
        #pragma unroll
        for (int tp = 0; tp < 2; tp++) {
            float pA = fmaxf(fmaxf(c[mt][2*tp][0], c[mt][2*tp][1]),
                             fmaxf(c[mt][2*tp+1][0], c[mt][2*tp+1][1]));
            float pB = fmaxf(fmaxf(c[mt][2*tp][2], c[mt][2*tp][3]),
                             fmaxf(c[mt][2*tp+1][2], c[mt][2*tp+1][3]));
            int gy = yh * 2 + tp;
            g_h1[bimg * FLAT + r0 * 16 + gy * 4 + lm4] = pA;
            g_h1[bimg * FLAT + (r0 + 8) * 16 + gy * 4 + lm4] = pB;
        }
        float s0 = 0.f, q0 = 0.f, s1 = 0.f, q1 = 0.f;
        #pragma unroll
        for (int nt = 0; nt < 4; nt++) {
            s0 += c[mt][nt][0] + c[mt][nt][1];
            q0 += c[mt][nt][0]*c[mt][nt][0] + c[mt][nt][1]*c[mt][nt][1];
            s1 += c[mt][nt][2] + c[mt][nt][3];
            q1 += c[mt][nt][2]*c[mt][nt][2] + c[mt][nt][3]*c[mt][nt][3];
        }
        s0 += __shfl_xor_sync(0xffffffffu, s0, 1); s0 += __shfl_xor_sync(0xffffffffu, s0, 2);
        q0 += __shfl_xor_sync(0xffffffffu, q0, 1); q0 += __shfl_xor_sync(0xffffffffu, q0, 2);
        s1 += __shfl_xor_sync(0xffffffffu, s1, 1); s1 += __shfl_xor_sync(0xffffffffu, s1, 2);
        q1 += __shfl_xor_sync(0xffffffffu, q1, 1); q1 += __shfl_xor_sync(0xffffffffu, q1, 2);
        if (lm4 == 0) {
            sps[(yh * 128 + r0) * 2 + img] = s0;       spq[(yh * 128 + r0) * 2 + img] = q0;
            sps[(yh * 128 + r0 + 8) * 2 + img] = s1;   spq[(yh * 128 + r0 + 8) * 2 + img] = q1;
        }
    }
    __syncthreads();
    {
        int oc = t >> 1, im = t & 1;
        float S = sps[(oc) * 2 + im] + sps[(128 + oc) * 2 + im];
        float Q = spq[(oc) * 2 + im] + spq[(128 + oc) * 2 + im];
        g_p2sum[oc * B + b2 + im] = S;
        g_p2sq [oc * B + b2 + im] = Q;
    }
}

// ---------------- fc1: fp16 mma + ldmatrix, 16-row b-tiles (grid 32x8, ~2 blocks/SM) ----
#define FC1_STR 136
__global__ __launch_bounds__(256) void k_fc1() {
    cudaTriggerProgrammaticLaunchCompletion();
    __shared__ __align__(16) __half sA[16 * FC1_STR];
    __shared__ __align__(16) __half sB[64 * FC1_STR];
    const int t = threadIdx.x;
    const int lane = t & 31, warp = t >> 5;
    const int l4 = lane >> 2, lm4 = lane & 3;
    const int b0 = blockIdx.x * 16, f0 = blockIdx.y * 64;
    const int n0w = warp * 8;                    // 8 warps x 8 features

    const unsigned sAa = (unsigned)__cvta_generic_to_shared(sA);
    const unsigned sBa = (unsigned)__cvta_generic_to_shared(sB);
    const unsigned aoff = (unsigned)((lane & 15) * FC1_STR) * 2u + (((unsigned)lane >> 4) << 4);
    const unsigned boff = (unsigned)((n0w + (lane & 7)) * FC1_STR) * 2u + ((((unsigned)lane >> 3) & 1u) << 4);

    float c[4];
    c[0] = c[1] = c[2] = c[3] = 0.f;

    for (int kc = 0; kc < 16; kc++) {
        if (kc) __syncthreads();
        // B first (weights provably complete; on kc==0 overlaps bnfin2 execution)
        #pragma unroll
        for (int j = 0; j < 4; j++) {
            int idx = t + 256 * j;
            int fl = idx >> 4, k8 = idx & 15;
            *(uint4*)&sB[fl * FC1_STR + k8 * 8] =
                *(const uint4*)&g_qf1h[(f0 + fl) * FLAT + kc * 128 + k8 * 8];
        }
        if (kc == 0) cudaGridDependencySynchronize();   // need scale2/shift2 from bnfin2
        // A: 16 rows x 128 k halves (BN2+ReLU from fp32 g_h1)
        #pragma unroll
        for (int j = 0; j < 4; j++) {
            int idx = t + 256 * j;                 // 0..1023 half2
            int bl = idx >> 6, kp = idx & 63;
            int kg = kc * 128 + 2 * kp;
            float2 v = *(const float2*)&g_h1[(b0 + bl) * FLAT + kg];
            int c0 = kg >> 4, c1 = (kg + 1) >> 4;
            float v0 = fmaxf(fmaf(g_scale2[c0], v.x, g_shift2[c0]), 0.0f);
            float v1 = fmaxf(fmaf(g_scale2[c1], v.y, g_shift2[c1]), 0.0f);
            *(__half2*)&sA[bl * FC1_STR + 2 * kp] = __floats2half2_rn(v0, v1);
        }
        __syncthreads();
        #pragma unroll
        for (int ks = 0; ks < 8; ks++) {
            const unsigned k0b = (unsigned)(ks * 32);
            unsigned a[4], bf[2];
            ldsm4(a[0], a[1], a[2], a[3], sAa + aoff + k0b);
            ldsm2(bf[0], bf[1], sBa + boff + k0b);
            asm volatile(
                "mma.sync.aligned.m16n8k16.row.col.f32.f16.f16.f32 "
                "{%0,%1,%2,%3},{%4,%5,%6,%7},{%8,%9},{%0,%1,%2,%3};"
                : "+f"(c[0]), "+f"(c[1]), "+f"(c[2]), "+f"(c[3])
                : "r"(a[0]), "r"(a[1]), "r"(a[2]), "r"(a[3]),
                  "r"(bf[0]), "r"(bf[1]));
        }
    }
    {
        int rA = b0 + l4;
        int cc = f0 + n0w + 2 * lm4;
        *(float2*)&g_fc1[rA * F1 + cc]       = make_float2(c[0], c[1]);
        *(float2*)&g_fc1[(rA + 8) * F1 + cc] = make_float2(c[2], c[3]);
    }
    // BN3 partials: per-feature sum/sumsq over this block's 16 batch rows
    __syncthreads();
    float* srs = (float*)sB;
    float* srq = srs + 64;
    #pragma unroll
    for (int j = 0; j < 2; j++) {
        float s = c[j] + c[j + 2];
        float q = c[j]*c[j] + c[j+2]*c[j+2];
        #pragma unroll
        for (int o = 4; o < 32; o <<= 1) {
            s += __shfl_xor_sync(0xffffffffu, s, o);
            q += __shfl_xor_sync(0xffffffffu, q, o);
        }
        if (l4 == 0) {
            int fl = n0w + 2 * lm4 + j;
            srs[fl] = s;
            srq[fl] = q;
        }
    }
    __syncthreads();
    if (t < 64) {
        g_p3s[(f0 + t) * 32 + blockIdx.x] = srs[t];
        g_p3q[(f0 + t) * 32 + blockIdx.x] = srq[t];
    }
}

// ---------------- fc2: 512 threads; all warps load weights, warps 0-7 compute -----------
__global__ __launch_bounds__(512) void k_fc2(const float* __restrict__ fc2_b,
                                             const float* __restrict__ bn3_g,
                                             const float* __restrict__ bn3_b,
                                             float* __restrict__ out) {
    cudaTriggerProgrammaticLaunchCompletion();
    __shared__ float swq[F2 * F1];
    __shared__ float sscale[F1], sshift[F1];
    __shared__ float sbias[F2];
    const int t = threadIdx.x;
    for (int i = t; i < F2 * F1; i += 512) swq[i] = g_qf2[i];   // quant done: overlap fc1
    if (t < F2) sbias[t] = fc2_b[t];
    cudaGridDependencySynchronize();             // need g_p3s/g_p3q/g_fc1 from fc1
    {
        int f = t;                                // 512 threads = 512 features
        float S = 0.f, Q = 0.f;
        #pragma unroll
        for (int u = 0; u < 8; u++) {
            float4 sv = *(const float4*)&g_p3s[f * 32 + 4 * u];
            float4 qv = *(const float4*)&g_p3q[f * 32 + 4 * u];
            S += sv.x + sv.y + sv.z + sv.w;
            Q += qv.x + qv.y + qv.z + qv.w;
        }
        const float invN = 1.0f / (float)B;
        float mean = S * invN;
        float var  = Q * invN - mean * mean;
        float sc = bn3_g[f] * rsqrtf(var + BN_EPS);
        sscale[f] = sc;
        sshift[f] = bn3_b[f] - mean * sc;
    }
    __syncthreads();
    const int warp = t >> 5, lane = t & 31;
    if (warp < 8) {
        const int b = blockIdx.x * 8 + warp;
        float h[16];
        #pragma unroll
        for (int i = 0; i < 16; i++) {
            int f = lane + 32 * i;
            float v = g_fc1[b * F1 + f];
            h[i] = fmaxf(fmaf(sscale[f], v, sshift[f]), 0.0f);
        }
        #pragma unroll
        for (int o = 0; o < F2; o++) {
            float acc = 0.f;
            #pragma unroll
            for (int i = 0; i < 16; i++)
                acc = fmaf(h[i], swq[o * F1 + lane + 32 * i], acc);
            #pragma unroll
            for (int s = 16; s; s >>= 1)
                acc += __shfl_xor_sync(0xffffffffu, acc, s);
            if (lane == 0) out[b * F2 + o] = acc + sbias[o];
        }
    }
}

// ---------------- PDL launch helper ----------------
template <typename... Args>
static void pdl_launch(void (*kern)(Args...), dim3 g, dim3 b, size_t smem, Args... args) {
    cudaLaunchConfig_t cfg = {};
    cfg.gridDim = g; cfg.blockDim = b; cfg.dynamicSmemBytes = smem; cfg.stream = 0;
    cudaLaunchAttribute at[1];
    at[0].id = cudaLaunchAttributeProgrammaticStreamSerialization;
    at[0].val.programmaticStreamSerializationAllowed = 1;
    cfg.attrs = at; cfg.numAttrs = 1;
    cudaLaunchKernelEx(&cfg, kern, args...);
}

// ---------------- launcher ----------------
extern "C" void kernel_launch(void* const* d_in, const int* in_sizes, int n_in,
                              void* d_out, int out_size) {
    const float* x       = (const float*)d_in[0];
    const float* conv1_w = (const float*)d_in[1];
    const float* bn1_g   = (const float*)d_in[3];
    const float* bn1_b   = (const float*)d_in[4];
    const float* conv2_w = (const float*)d_in[5];
    const float* bn2_g   = (const float*)d_in[7];
    const float* bn2_b   = (const float*)d_in[8];
    const float* fc1_w   = (const float*)d_in[9];
    const float* bn3_g   = (const float*)d_in[11];
    const float* bn3_b   = (const float*)d_in[12];
    const float* fc2_w   = (const float*)d_in[13];
    const float* fc2_b   = (const float*)d_in[14];
    float* out = (float*)d_out;

    cudaFuncSetAttribute(k_conv1, cudaFuncAttributeMaxDynamicSharedMemorySize, CV1_SMEM_BYTES);
    cudaFuncSetAttribute(k_conv2, cudaFuncAttributeMaxDynamicSharedMemorySize, CV2_SMEM_BYTES);

    // weight quantization for conv2/fc1/fc2 (conv1 self-quantizes inside k_conv1)
    pdl_launch(k_absmax_all, dim3(128, 3), dim3(256), 0, conv2_w, fc1_w, fc2_w);
    pdl_launch(k_quant_all,  dim3(128, 3), dim3(256), 0, conv2_w, fc1_w, fc2_w);

    // stage 1: conv1 is dependency-free -> overlaps absmax AND quant
    pdl_launch(k_conv1, dim3(B), dim3(256), (size_t)CV1_SMEM_BYTES, x, conv1_w);
    pdl_launch(k_bnfin1, dim3(C1), dim3(32), 0, bn1_g, bn1_b);   // gates cascade

    // stage 2 (weight staging overlaps bnfin1 execution; double-buffered cp.async)
    pdl_launch(k_conv2, dim3(B / 2), dim3(256), (size_t)CV2_SMEM_BYTES);
    pdl_launch(k_bnfin2, dim3(C2), dim3(32), 0, bn2_g, bn2_b);   // gates cascade

    // stage 3 (fc1: 256 blocks for ~2/SM occupancy; fc2 weight load overlaps fc1)
    pdl_launch(k_fc1, dim3(32, 8), dim3(256), 0);
    pdl_launch(k_fc2, dim3(B / 8), dim3(512), 0, fc2_b, bn3_g, bn3_b, out);
}

// round 17
// speedup vs baseline: 1.1549x; 1.1549x over previous
#include <cuda_runtime.h>
#include <cuda_fp16.h>
#include <cuda_bf16.h>

// ---------------- problem constants ----------------
#define B      512
#define C1     64
#define C2     128
#define FLAT   2048
#define F1     512
#define F2     10
#define BN_EPS 1e-5f

// ---------------- device scratch ----------------
__device__ unsigned g_maxabs[4];                  // slots 1..3; zero-init; atomicMax idempotent
__device__ __half g_qw2h[25 * C2 * C1];           // conv2 ternary [khkw][oc][ci]
__device__ __half g_qf1h[F1 * FLAT];              // fc1 ternary [f][k]
__device__ float  g_qf2[F2 * F1];
__device__ float g_pool1[B * 144 * C1];           // RAW pooled conv1 (pre-BN), [b][pixel][ci]
__device__ float g_p1sum[C1 * B], g_p1sq[C1 * B];
__device__ float g_scale1[C1], g_shift1[C1];
__device__ float g_p2sum[C2 * B], g_p2sq[C2 * B];
__device__ float g_scale2[C2], g_shift2[C2];
__device__ float g_h1[B * FLAT];                  // RAW pooled conv2 (pre-BN)
__device__ float g_fc1[B * F1];                   // RAW fc1 (pre-BN)
__device__ float g_p3s[F1 * 16], g_p3q[F1 * 16];  // BN3 partials: [feature][b-tile]

// ---------------- asm helpers ----------------
__device__ __forceinline__ void cp16(void* smem_dst, const void* gsrc) {
    unsigned s = (unsigned)__cvta_generic_to_shared(smem_dst);
    asm volatile("cp.async.cg.shared.global [%0], [%1], 16;\n" :: "r"(s), "l"(gsrc));
}
#define CP_COMMIT() asm volatile("cp.async.commit_group;\n" ::: "memory")
#define CP_WAIT0()  asm volatile("cp.async.wait_group 0;\n" ::: "memory")

__device__ __forceinline__ void ldsm4(unsigned& r0, unsigned& r1, unsigned& r2, unsigned& r3,
                                      unsigned saddr) {
    asm volatile("ldmatrix.sync.aligned.m8n8.x4.shared.b16 {%0,%1,%2,%3}, [%4];"
                 : "=r"(r0), "=r"(r1), "=r"(r2), "=r"(r3) : "r"(saddr));
}
__device__ __forceinline__ void ldsm2(unsigned& r0, unsigned& r1, unsigned saddr) {
    asm volatile("ldmatrix.sync.aligned.m8n8.x2.shared.b16 {%0,%1}, [%2];"
                 : "=r"(r0), "=r"(r1) : "r"(saddr));
}

// ---------------- quantization (slots 1..3: conv2, fc1, fc2 weights) ----------------
__global__ void k_absmax_all(const float* __restrict__ w1, const float* __restrict__ w2,
                             const float* __restrict__ w3) {
    cudaTriggerProgrammaticLaunchCompletion();
    const int slot = blockIdx.y + 1;
    const float* w = (slot == 1) ? w1 : (slot == 2) ? w2 : w3;
    const int n4 = ((slot == 1) ? 204800 : (slot == 2) ? 1048576 : 5120) >> 2;
    const float4* w4 = (const float4*)w;
    unsigned m = 0u;
    #pragma unroll 4
    for (int i = blockIdx.x * blockDim.x + threadIdx.x; i < n4; i += gridDim.x * blockDim.x) {
        float4 v = w4[i];
        m = max(m, __float_as_uint(fabsf(v.x)));
        m = max(m, __float_as_uint(fabsf(v.y)));
        m = max(m, __float_as_uint(fabsf(v.z)));
        m = max(m, __float_as_uint(fabsf(v.w)));
    }
    #pragma unroll
    for (int o = 16; o; o >>= 1)
        m = max(m, __shfl_xor_sync(0xffffffffu, m, o));
    if ((threadIdx.x & 31) == 0) atomicMax(&g_maxabs[slot], m);
}

__global__ void k_quant_all(const float* __restrict__ w1,
                            const float* __restrict__ w2, const float* __restrict__ w3) {
    cudaTriggerProgrammaticLaunchCompletion();   // conv1 is self-contained: safe to cascade
    cudaGridDependencySynchronize();             // need g_maxabs from absmax
    const int slot = blockIdx.y + 1;
    const float* w = (slot == 1) ? w1 : (slot == 2) ? w2 : w3;
    const int n4 = ((slot == 1) ? 204800 : (slot == 2) ? 1048576 : 5120) >> 2;
    const float4* w4 = (const float4*)w;
    const float t = 0.05f * __uint_as_float(g_maxabs[slot]);
    #pragma unroll 2
    for (int i = blockIdx.x * blockDim.x + threadIdx.x; i < n4; i += gridDim.x * blockDim.x) {
        float4 v = w4[i];
        float q0 = (v.x > t) ? 1.0f : ((v.x < -t) ? -1.0f : 0.0f);
        float q1 = (v.y > t) ? 1.0f : ((v.y < -t) ? -1.0f : 0.0f);
        float q2 = (v.z > t) ? 1.0f : ((v.z < -t) ? -1.0f : 0.0f);
        float q3 = (v.w > t) ? 1.0f : ((v.w < -t) ? -1.0f : 0.0f);
        int base = 4 * i;
        if (slot == 1) {
            float qs[4] = {q0, q1, q2, q3};
            #pragma unroll
            for (int u = 0; u < 4; u++) {
                int idx = base + u;
                int oc = idx / 1600, rem = idx - oc * 1600, ci = rem / 25, kk = rem - ci * 25;
                g_qw2h[kk * (C2 * C1) + oc * C1 + ci] = __float2half(qs[u]);
            }
        } else if (slot == 2) {
            *(__half2*)&g_qf1h[base]     = __floats2half2_rn(q0, q1);
            *(__half2*)&g_qf1h[base + 2] = __floats2half2_rn(q2, q3);
        } else {
            *(float4*)&g_qf2[base] = make_float4(q0, q1, q2, q3);
        }
    }
}

// ---------------- conv1: fp16 mma; fully self-contained (own absmax + quant) ------------
// x staged via cp.async: fetch latency hidden under the weight-absmax phase.
#define CV1_SMEM_BYTES (3136 + 5120 + 46080)
__global__ __launch_bounds__(256) void k_conv1(const float* __restrict__ x,
                                               const float* __restrict__ w1raw) {
    cudaTriggerProgrammaticLaunchCompletion();
    extern __shared__ char c1sm[];
    float*  sxf = (float*)c1sm;
    __half* sA  = (__half*)(c1sm + 3136);
    __half* sB  = (__half*)(c1sm + 3136 + 5120);
    __shared__ float srs[64][9], srq[64][9];
    __shared__ unsigned swm[8];
    const int b = blockIdx.x, t = threadIdx.x;
    const int lane = t & 31, warp = t >> 5;
    const int l4 = lane >> 2, lm4 = lane & 3;

    if (t < 196) cp16(&sxf[t * 4], &x[b * 784 + t * 4]);   // 784 floats = 196 x 16B
    CP_COMMIT();
    {
        unsigned mm = 0u;
        for (int i = t; i < 1600; i += 256) mm = max(mm, __float_as_uint(fabsf(w1raw[i])));
        #pragma unroll
        for (int o = 16; o; o >>= 1) mm = max(mm, __shfl_xor_sync(0xffffffffu, mm, o));
        if (lane == 0) swm[warp] = mm;
    }
    __syncthreads();
    {
        unsigned m8 = swm[0];
        #pragma unroll
        for (int j = 1; j < 8; j++) m8 = max(m8, swm[j]);
        const float tq = 0.05f * __uint_as_float(m8);
        for (int i = t; i < 1600; i += 256) {
            int oc = i / 25, k = i - oc * 25;
            float v = w1raw[i];
            sA[oc * 40 + k] = __float2half((v > tq) ? 1.0f : ((v < -tq) ? -1.0f : 0.0f));
        }
        for (int i = t; i < 64 * 7; i += 256) {
            int oc = i / 7, k = 25 + i % 7;
            sA[oc * 40 + k] = __ushort_as_half((unsigned short)0);
        }
    }
    CP_WAIT0();
    __syncthreads();          // all x chunks visible block-wide before im2col
    {
        const int kp = t & 15, n0 = t >> 4;
        const int k0 = 2 * kp;
        const int kh0 = k0 / 5, kw0 = k0 - 5 * kh0;
        const int kh1 = (k0 + 1) / 5, kw1 = (k0 + 1) - 5 * kh1;
        const bool e0 = (k0 < 25), e1 = (k0 + 1 < 25);
        #pragma unroll 4
        for (int st = 0; st < 36; st++) {
            int n = n0 + 16 * st;
            int w = n >> 2, j = n & 3;
            int py = w / 12, px = w - 12 * py;
            int iy = 2 * py + (j >> 1), ix = 2 * px + (j & 1);
            float v0 = e0 ? sxf[(iy + kh0) * 28 + ix + kw0] : 0.f;
            float v1 = e1 ? sxf[(iy + kh1) * 28 + ix + kw1] : 0.f;
            *(__half2*)&sB[n * 40 + k0] = __floats2half2_rn(v0, v1);
        }
    }
    __syncthreads();

    unsigned a[4][2][4];
    #pragma unroll
    for (int mt = 0; mt < 4; mt++) {
        const __half* ap = sA + (mt * 16 + l4) * 40 + 2 * lm4;
        #pragma unroll
        for (int ks = 0; ks < 2; ks++) {
            a[mt][ks][0] = *(const unsigned*)(ap + 16 * ks);
            a[mt][ks][1] = *(const unsigned*)(ap + 16 * ks + 8 * 40);
            a[mt][ks][2] = *(const unsigned*)(ap + 16 * ks + 8);
            a[mt][ks][3] = *(const unsigned*)(ap + 16 * ks + 8 * 40 + 8);
        }
    }

    float s0a[4] = {0,0,0,0}, s1a[4] = {0,0,0,0};
    float q0a[4] = {0,0,0,0}, q1a[4] = {0,0,0,0};

    #pragma unroll
    for (int nt = 0; nt < 9; nt++) {
        const __half* bp = sB + (warp * 72 + nt * 8 + l4) * 40 + 2 * lm4;
        unsigned bf[2][2];
        #pragma unroll
        for (int ks = 0; ks < 2; ks++) {
            bf[ks][0] = *(const unsigned*)(bp + 16 * ks);
            bf[ks][1] = *(const unsigned*)(bp + 16 * ks + 8);
        }
        float c[4][4];
        #pragma unroll
        for (int mt = 0; mt < 4; mt++) {
            c[mt][0] = c[mt][1] = c[mt][2] = c[mt][3] = 0.f;
            #pragma unroll
            for (int ks = 0; ks < 2; ks++)
                asm volatile(
                    "mma.sync.aligned.m16n8k16.row.col.f32.f16.f16.f32 "
                    "{%0,%1,%2,%3},{%4,%5,%6,%7},{%8,%9},{%0,%1,%2,%3};"
                    : "+f"(c[mt][0]), "+f"(c[mt][1]), "+f"(c[mt][2]), "+f"(c[mt][3])
                    : "r"(a[mt][ks][0]), "r"(a[mt][ks][1]), "r"(a[mt][ks][2]), "r"(a[mt][ks][3]),
                      "r"(bf[ks][0]), "r"(bf[ks][1]));
        }
        const int wdw = warp * 18 + nt * 2 + (lm4 >> 1);
        #pragma unroll
        for (int mt = 0; mt < 4; mt++) {
            s0a[mt] += c[mt][0] + c[mt][1];
            q0a[mt] += c[mt][0]*c[mt][0] + c[mt][1]*c[mt][1];
            s1a[mt] += c[mt][2] + c[mt][3];
            q1a[mt] += c[mt][2]*c[mt][2] + c[mt][3]*c[mt][3];
            float m0 = fmaxf(c[mt][0], c[mt][1]);
            float m1 = fmaxf(c[mt][2], c[mt][3]);
            m0 = fmaxf(m0, __shfl_xor_sync(0xffffffffu, m0, 1));
            m1 = fmaxf(m1, __shfl_xor_sync(0xffffffffu, m1, 1));
            if ((lm4 & 1) == 0) {
                int oc = mt * 16 + l4;
                g_pool1[b * 9216 + wdw * 64 + oc]     = m0;
                g_pool1[b * 9216 + wdw * 64 + oc + 8] = m1;
            }
        }
    }

    #pragma unroll
    for (int mt = 0; mt < 4; mt++) {
        float s0 = s0a[mt], q0 = q0a[mt], s1 = s1a[mt], q1 = q1a[mt];
        s0 += __shfl_xor_sync(0xffffffffu, s0, 1); s0 += __shfl_xor_sync(0xffffffffu, s0, 2);
        q0 += __shfl_xor_sync(0xffffffffu, q0, 1); q0 += __shfl_xor_sync(0xffffffffu, q0, 2);
        s1 += __shfl_xor_sync(0xffffffffu, s1, 1); s1 += __shfl_xor_sync(0xffffffffu, s1, 2);
        q1 += __shfl_xor_sync(0xffffffffu, q1, 1); q1 += __shfl_xor_sync(0xffffffffu, q1, 2);
        if (lm4 == 0) {
            srs[mt * 16 + l4][warp] = s0;     srq[mt * 16 + l4][warp] = q0;
            srs[mt * 16 + l4 + 8][warp] = s1; srq[mt * 16 + l4 + 8][warp] = q1;
        }
    }
    __syncthreads();
    if (t < 64) {
        float S = 0.f, Q = 0.f;
        #pragma unroll
        for (int w = 0; w < 8; w++) { S += srs[t][w]; Q += srq[t][w]; }
        g_p1sum[t * B + b] = S;
        g_p1sq [t * B + b] = Q;
    }
}

// ---------------- BN finalize: one 32-thread block per channel ----------------
__global__ void k_bnfin1(const float* __restrict__ gamma, const float* __restrict__ beta) {
    cudaGridDependencySynchronize();
    cudaTriggerProgrammaticLaunchCompletion();   // gate: conv2 may launch now
    const int lane = threadIdx.x & 31;
    const int c = blockIdx.x;
    const float4* ps = (const float4*)&g_p1sum[c * B];
    const float4* pq = (const float4*)&g_p1sq [c * B];
    float s = 0.f, q = 0.f;
    #pragma unroll
    for (int i = 0; i < 4; i++) {
        float4 v = ps[lane * 4 + i]; s += v.x + v.y + v.z + v.w;
        float4 u = pq[lane * 4 + i]; q += u.x + u.y + u.z + u.w;
    }
    #pragma unroll
    for (int o = 16; o; o >>= 1) {
        s += __shfl_xor_sync(0xffffffffu, s, o);
        q += __shfl_xor_sync(0xffffffffu, q, o);
    }
    if (lane == 0) {
        const float invN = 1.0f / (float)(B * 576);
        float mean = s * invN;
        float var  = q * invN - mean * mean;
        float sc = gamma[c] * rsqrtf(var + BN_EPS);
        g_scale1[c] = sc;
        g_shift1[c] = beta[c] - mean * sc;
    }
}

__global__ void k_bnfin2(const float* __restrict__ gamma, const float* __restrict__ beta) {
    cudaGridDependencySynchronize();
    cudaTriggerProgrammaticLaunchCompletion();   // gate: fc1 may launch now
    const int lane = threadIdx.x & 31;
    const int c = blockIdx.x;
    const float4* ps = (const float4*)&g_p2sum[c * B];
    const float4* pq = (const float4*)&g_p2sq [c * B];
    float s = 0.f, q = 0.f;
    #pragma unroll
    for (int i = 0; i < 4; i++) {
        float4 v = ps[lane * 4 + i]; s += v.x + v.y + v.z + v.w;
        float4 u = pq[lane * 4 + i]; q += u.x + u.y + u.z + u.w;
    }
    #pragma unroll
    for (int o = 16; o; o >>= 1) {
        s += __shfl_xor_sync(0xffffffffu, s, o);
        q += __shfl_xor_sync(0xffffffffu, q, o);
    }
    if (lane == 0) {
        const float invN = 1.0f / (float)(B * 64);
        float mean = s * invN;
        float var  = q * invN - mean * mean;
        float sc = gamma[c] * rsqrtf(var + BN_EPS);
        g_scale2[c] = sc;
        g_shift2[c] = beta[c] - mean * sc;
    }
}

// ---------------- conv2: fp16 mma + ldmatrix frags, 2 images/block, 2 blocks/SM ---------
#define CV2_CSTR 72
#define CV2_IMGH (144 * CV2_CSTR)
#define CV2_SX_H (2 * CV2_IMGH)
#define CV2_WBUF (C2 * CV2_CSTR)
#define CV2_SMEM_BYTES ((CV2_SX_H + 2 * CV2_WBUF) * 2)

__global__ __launch_bounds__(256, 2) void k_conv2() {
    cudaTriggerProgrammaticLaunchCompletion();
    extern __shared__ __half smh[];
    __half* sxh = smh;
    __half* sA0 = smh + CV2_SX_H;
    __half* sA1 = sA0 + CV2_WBUF;
    const int b2 = blockIdx.x * 2;
    const int t = threadIdx.x;
    const int lane = t & 31, warp = t >> 5;
    const int l4 = lane >> 2, lm4 = lane & 3;
    const int wm = warp >> 2, wn = warp & 3;
    const int img = wn >> 1, yh = wn & 1;
    const int m0w = wm * 64;

    {   // weights provably complete (launched after bnfin1's post-sync trigger)
        const __half* wsrc = g_qw2h;
        #pragma unroll
        for (int j = 0; j < 4; j++) {
            int idx = t + 256 * j;
            int oc = idx >> 3, c8 = idx & 7;
            cp16(sA0 + oc * CV2_CSTR + c8 * 8, wsrc + idx * 8);
        }
        CP_COMMIT();
    }

    cudaGridDependencySynchronize();             // need scale1/shift1 from bnfin1

    for (int idx = t; idx < 2 * 144 * 32; idx += 256) {
        int im = idx / 4608, r = idx - im * 4608;
        int p = r >> 5, cp = r & 31;
        int ci0 = 2 * cp;
        float2 v = *(const float2*)&g_pool1[(b2 + im) * 9216 + p * 64 + ci0];
        float v0 = fmaxf(fmaf(g_scale1[ci0],     v.x, g_shift1[ci0]),     0.0f);
        float v1 = fmaxf(fmaf(g_scale1[ci0 + 1], v.y, g_shift1[ci0 + 1]), 0.0f);
        *(__half2*)&sxh[im * CV2_IMGH + p * CV2_CSTR + ci0] = __floats2half2_rn(v0, v1);
    }

    float c[4][4][4];
    #pragma unroll
    for (int i = 0; i < 4; i++)
        #pragma unroll
        for (int j = 0; j < 4; j++)
            #pragma unroll
            for (int r = 0; r < 4; r++) c[i][j][r] = 0.f;

    const unsigned sxa  = (unsigned)__cvta_generic_to_shared(sxh);
    const unsigned sA0a = (unsigned)__cvta_generic_to_shared(sA0);
    const unsigned sA1a = (unsigned)__cvta_generic_to_shared(sA1);
    const unsigned aoff = (unsigned)((m0w + (lane & 15)) * CV2_CSTR) * 2u + (((unsigned)lane >> 4) << 4);
    const unsigned bln  = (unsigned)((lane & 7) * CV2_CSTR) * 2u + ((((unsigned)lane >> 3) & 1u) << 4);

    for (int khkw = 0; khkw < 25; khkw++) {
        const unsigned sAa = (khkw & 1) ? sA1a : sA0a;
        CP_WAIT0();
        __syncthreads();
        if (khkw < 24) {
            __half* dst = (khkw & 1) ? sA0 : sA1;
            const __half* wsrc = g_qw2h + (khkw + 1) * (C2 * C1);
            #pragma unroll
            for (int j = 0; j < 4; j++) {
                int idx = t + 256 * j;
                int oc = idx >> 3, c8 = idx & 7;
                cp16(dst + oc * CV2_CSTR + c8 * 8, wsrc + idx * 8);
            }
            CP_COMMIT();
        }
        const int kh = khkw / 5, kw = khkw - 5 * kh;
        const unsigned bbase = sxa
            + (unsigned)(img * CV2_IMGH + ((yh * 4 + kh) * 12 + kw) * CV2_CSTR) * 2u + bln;
        #pragma unroll
        for (int ks = 0; ks < 4; ks++) {
            const unsigned k0b = (unsigned)(ks * 32);
            unsigned a[4][4], bf[4][2];
            #pragma unroll
            for (int mt = 0; mt < 4; mt++)
                ldsm4(a[mt][0], a[mt][1], a[mt][2], a[mt][3],
                      sAa + aoff + (unsigned)(mt * 16 * CV2_CSTR * 2) + k0b);
            #pragma unroll
            for (int nt = 0; nt < 4; nt++)
                ldsm2(bf[nt][0], bf[nt][1],
                      bbase + (unsigned)(nt * 12 * CV2_CSTR * 2) + k0b);
            #pragma unroll
            for (int mt = 0; mt < 4; mt++)
                #pragma unroll
                for (int nt = 0; nt < 4; nt++)
                    asm volatile(
                        "mma.sync.aligned.m16n8k16.row.col.f32.f16.f16.f32 "
                        "{%0,%1,%2,%3},{%4,%5,%6,%7},{%8,%9},{%0,%1,%2,%3};"
                        : "+f"(c[mt][nt][0]), "+f"(c[mt][nt][1]),
                          "+f"(c[mt][nt][2]), "+f"(c[mt][nt][3])
                        : "r"(a[mt][0]), "r"(a[mt][1]), "r"(a[mt][2]), "r"(a[mt][3]),
                          "r"(bf[nt][0]), "r"(bf[nt][1]));
        }
    }

    __syncthreads();
    float* sps = (float*)sA0;
    float* spq = sps + 512;
    const int bimg = b2 + img;
    #pragma unroll
    for (int mt = 0; mt < 4; mt++) {
        int r0 = m0w + mt * 16 + l4;
        #pragma unroll
        for (int tp = 0; tp < 2; tp++) {
            float pA = fmaxf(fmaxf(c[mt][2*tp][0], c[mt][2*tp][1]),
                             fmaxf(c[mt][2*tp+1][0], c[mt][2*tp+1][1]));
            float pB = fmaxf(fmaxf(c[mt][2*tp][2], c[mt][2*tp][3]),
                             fmaxf(c[mt][2*tp+1][2], c[mt][2*tp+1][3]));
            int gy = yh * 2 + tp;
            g_h1[bimg * FLAT + r0 * 16 + gy * 4 + lm4] = pA;
            g_h1[bimg * FLAT + (r0 + 8) * 16 + gy * 4 + lm4] = pB;
        }
        float s0 = 0.f, q0 = 0.f, s1 = 0.f, q1 = 0.f;
        #pragma unroll
        for (int nt = 0; nt < 4; nt++) {
            s0 += c[mt][nt][0] + c[mt][nt][1];
            q0 += c[mt][nt][0]*c[mt][nt][0] + c[mt][nt][1]*c[mt][nt][1];
            s1 += c[mt][nt][2] + c[mt][nt][3];
            q1 += c[mt][nt][2]*c[mt][nt][2] + c[mt][nt][3]*c[mt][nt][3];
        }
        s0 += __shfl_xor_sync(0xffffffffu, s0, 1); s0 += __shfl_xor_sync(0xffffffffu, s0, 2);
        q0 += __shfl_xor_sync(0xffffffffu, q0, 1); q0 += __shfl_xor_sync(0xffffffffu, q0, 2);
        s1 += __shfl_xor_sync(0xffffffffu, s1, 1); s1 += __shfl_xor_sync(0xffffffffu, s1, 2);
        q1 += __shfl_xor_sync(0xffffffffu, q1, 1); q1 += __shfl_xor_sync(0xffffffffu, q1, 2);
        if (lm4 == 0) {
            sps[(yh * 128 + r0) * 2 + img] = s0;       spq[(yh * 128 + r0) * 2 + img] = q0;
            sps[(yh * 128 + r0 + 8) * 2 + img] = s1;   spq[(yh * 128 + r0 + 8) * 2 + img] = q1;
        }
    }
    __syncthreads();
    {
        int oc = t >> 1, im = t & 1;
        float S = sps[(oc) * 2 + im] + sps[(128 + oc) * 2 + im];
        float Q = spq[(oc) * 2 + im] + spq[(128 + oc) * 2 + im];
        g_p2sum[oc * B + b2 + im] = S;
        g_p2sq [oc * B + b2 + im] = Q;
    }
}

// ---------------- fc1: fp16 mma + ldmatrix frags, 32-row b-tiles (grid 16x8) ------------
#define FC1_STR 136
__global__ __launch_bounds__(256) void k_fc1() {
    cudaTriggerProgrammaticLaunchCompletion();
    __shared__ __align__(16) __half sA[32 * FC1_STR];
    __shared__ __align__(16) __half sB[64 * FC1_STR];
    const int t = threadIdx.x;
    const int lane = t & 31, warp = t >> 5;
    const int l4 = lane >> 2, lm4 = lane & 3;
    const int wm = warp >> 2, wn = warp & 3;
    const int b0 = blockIdx.x * 32, f0 = blockIdx.y * 64;
    const int m0w = wm * 16, n0w = wn * 16;

    const unsigned sAa = (unsigned)__cvta_generic_to_shared(sA);
    const unsigned sBa = (unsigned)__cvta_generic_to_shared(sB);
    const unsigned aoff = (unsigned)((m0w + (lane & 15)) * FC1_STR) * 2u + (((unsigned)lane >> 4) << 4);
    const unsigned boff = (unsigned)((n0w + (lane & 7)) * FC1_STR) * 2u + ((((unsigned)lane >> 3) & 1u) << 4);

    float c[2][4];
    #pragma unroll
    for (int j = 0; j < 2; j++)
        #pragma unroll
        for (int r = 0; r < 4; r++) c[j][r] = 0.f;

    for (int kc = 0; kc < 16; kc++) {
        if (kc) __syncthreads();
        // B first (weights provably complete; on kc==0 overlaps bnfin2 execution)
        #pragma unroll
        for (int j = 0; j < 4; j++) {
            int idx = t + 256 * j;
            int fl = idx >> 4, k8 = idx & 15;
            *(uint4*)&sB[fl * FC1_STR + k8 * 8] =
                *(const uint4*)&g_qf1h[(f0 + fl) * FLAT + kc * 128 + k8 * 8];
        }
        if (kc == 0) cudaGridDependencySynchronize();   // need scale2/shift2 from bnfin2
        #pragma unroll
        for (int j = 0; j < 8; j++) {
            int idx = t + 256 * j;
            int bl = idx >> 6, kp = idx & 63;
            int kg = kc * 128 + 2 * kp;
            float2 v = *(const float2*)&g_h1[(b0 + bl) * FLAT + kg];
            int c0 = kg >> 4, c1 = (kg + 1) >> 4;
            float v0 = fmaxf(fmaf(g_scale2[c0], v.x, g_shift2[c0]), 0.0f);
            float v1 = fmaxf(fmaf(g_scale2[c1], v.y, g_shift2[c1]), 0.0f);
            *(__half2*)&sA[bl * FC1_STR + 2 * kp] = __floats2half2_rn(v0, v1);
        }
        __syncthreads();
        #pragma unroll
        for (int ks = 0; ks < 8; ks++) {
            const unsigned k0b = (unsigned)(ks * 32);
            unsigned a[4], bf[2][2];
            ldsm4(a[0], a[1], a[2], a[3], sAa + aoff + k0b);
            #pragma unroll
            for (int nt = 0; nt < 2; nt++)
                ldsm2(bf[nt][0], bf[nt][1],
                      sBa + boff + (unsigned)(nt * 8 * FC1_STR * 2) + k0b);
            #pragma unroll
            for (int nt = 0; nt < 2; nt++)
                asm volatile(
                    "mma.sync.aligned.m16n8k16.row.col.f32.f16.f16.f32 "
                    "{%0,%1,%2,%3},{%4,%5,%6,%7},{%8,%9},{%0,%1,%2,%3};"
                    : "+f"(c[nt][0]), "+f"(c[nt][1]), "+f"(c[nt][2]), "+f"(c[nt][3])
                    : "r"(a[0]), "r"(a[1]), "r"(a[2]), "r"(a[3]),
                      "r"(bf[nt][0]), "r"(bf[nt][1]));
        }
    }
    {
        int rA = b0 + m0w + l4;
        #pragma unroll
        for (int nt = 0; nt < 2; nt++) {
            int cc = f0 + n0w + nt * 8 + 2 * lm4;
            *(float2*)&g_fc1[rA * F1 + cc]       = make_float2(c[nt][0], c[nt][1]);
            *(float2*)&g_fc1[(rA + 8) * F1 + cc] = make_float2(c[nt][2], c[nt][3]);
        }
    }
    __syncthreads();
    float* srs = (float*)sB;
    float* srq = srs + 128;
    #pragma unroll
    for (int nt = 0; nt < 2; nt++) {
        #pragma unroll
        for (int j = 0; j < 2; j++) {
            float s = c[nt][j] + c[nt][j + 2];
            float q = c[nt][j]*c[nt][j] + c[nt][j+2]*c[nt][j+2];
            #pragma unroll
            for (int o = 4; o < 32; o <<= 1) {
                s += __shfl_xor_sync(0xffffffffu, s, o);
                q += __shfl_xor_sync(0xffffffffu, q, o);
            }
            if (l4 == 0) {
                int fl = n0w + nt * 8 + 2 * lm4 + j;
                srs[wm * 64 + fl] = s;
                srq[wm * 64 + fl] = q;
            }
        }
    }
    __syncthreads();
    if (t < 64) {
        float S = srs[t] + srs[64 + t];
        float Q = srq[t] + srq[64 + t];
        g_p3s[(f0 + t) * 16 + blockIdx.x] = S;
        g_p3q[(f0 + t) * 16 + blockIdx.x] = Q;
    }
}

// ---------------- fc2: 512 threads; all warps load weights, warps 0-7 compute -----------
__global__ __launch_bounds__(512) void k_fc2(const float* __restrict__ fc2_b,
                                             const float* __restrict__ bn3_g,
                                             const float* __restrict__ bn3_b,
                                             float* __restrict__ out) {
    cudaTriggerProgrammaticLaunchCompletion();
    __shared__ float swq[F2 * F1];
    __shared__ float sscale[F1], sshift[F1];
    __shared__ float sbias[F2];
    const int t = threadIdx.x;
    for (int i = t; i < F2 * F1; i += 512) swq[i] = g_qf2[i];   // quant done: overlap fc1
    if (t < F2) sbias[t] = fc2_b[t];
    cudaGridDependencySynchronize();             // need g_p3s/g_p3q/g_fc1 from fc1
    {
        int f = t;                                // 512 threads = 512 features
        float S = 0.f, Q = 0.f;
        #pragma unroll
        for (int u = 0; u < 4; u++) {
            float4 sv = *(const float4*)&g_p3s[f * 16 + 4 * u];
            float4 qv = *(const float4*)&g_p3q[f * 16 + 4 * u];
            S += sv.x + sv.y + sv.z + sv.w;
            Q += qv.x + qv.y + qv.z + qv.w;
        }
        const float invN = 1.0f / (float)B;
        float mean = S * invN;
        float var  = Q * invN - mean * mean;
        float sc = bn3_g[f] * rsqrtf(var + BN_EPS);
        sscale[f] = sc;
        sshift[f] = bn3_b[f] - mean * sc;
    }
    __syncthreads();
    const int warp = t >> 5, lane = t & 31;
    if (warp < 8) {
        const int b = blockIdx.x * 8 + warp;
        float h[16];
        #pragma unroll
        for (int i = 0; i < 16; i++) {
            int f = lane + 32 * i;
            float v = g_fc1[b * F1 + f];
            h[i] = fmaxf(fmaf(sscale[f], v, sshift[f]), 0.0f);
        }
        #pragma unroll
        for (int o = 0; o < F2; o++) {
            float acc = 0.f;
            #pragma unroll
            for (int i = 0; i < 16; i++)
                acc = fmaf(h[i], swq[o * F1 + lane + 32 * i], acc);
            #pragma unroll
            for (int s = 16; s; s >>= 1)
                acc += __shfl_xor_sync(0xffffffffu, acc, s);
            if (lane == 0) out[b * F2 + o] = acc + sbias[o];
        }
    }
}

// ---------------- PDL launch helper ----------------
template <typename... Args>
static void pdl_launch(void (*kern)(Args...), dim3 g, dim3 b, size_t smem, Args... args) {
    cudaLaunchConfig_t cfg = {};
    cfg.gridDim = g; cfg.blockDim = b; cfg.dynamicSmemBytes = smem; cfg.stream = 0;
    cudaLaunchAttribute at[1];
    at[0].id = cudaLaunchAttributeProgrammaticStreamSerialization;
    at[0].val.programmaticStreamSerializationAllowed = 1;
    cfg.attrs = at; cfg.numAttrs = 1;
    cudaLaunchKernelEx(&cfg, kern, args...);
}

// ---------------- launcher ----------------
extern "C" void kernel_launch(void* const* d_in, const int* in_sizes, int n_in,
                              void* d_out, int out_size) {
    const float* x       = (const float*)d_in[0];
    const float* conv1_w = (const float*)d_in[1];
    const float* bn1_g   = (const float*)d_in[3];
    const float* bn1_b   = (const float*)d_in[4];
    const float* conv2_w = (const float*)d_in[5];
    const float* bn2_g   = (const float*)d_in[7];
    const float* bn2_b   = (const float*)d_in[8];
    const float* fc1_w   = (const float*)d_in[9];
    const float* bn3_g   = (const float*)d_in[11];
    const float* bn3_b   = (const float*)d_in[12];
    const float* fc2_w   = (const float*)d_in[13];
    const float* fc2_b   = (const float*)d_in[14];
    float* out = (float*)d_out;

    cudaFuncSetAttribute(k_conv1, cudaFuncAttributeMaxDynamicSharedMemorySize, CV1_SMEM_BYTES);
    cudaFuncSetAttribute(k_conv2, cudaFuncAttributeMaxDynamicSharedMemorySize, CV2_SMEM_BYTES);

    // weight quantization for conv2/fc1/fc2 (conv1 self-quantizes inside k_conv1)
    pdl_launch(k_absmax_all, dim3(128, 3), dim3(256), 0, conv2_w, fc1_w, fc2_w);
    pdl_launch(k_quant_all,  dim3(128, 3), dim3(256), 0, conv2_w, fc1_w, fc2_w);

    // stage 1: conv1 is dependency-free -> overlaps absmax AND quant
    pdl_launch(k_conv1, dim3(B), dim3(256), (size_t)CV1_SMEM_BYTES, x, conv1_w);
    pdl_launch(k_bnfin1, dim3(C1), dim3(32), 0, bn1_g, bn1_b);   // gates cascade

    // stage 2 (weight staging overlaps bnfin1 execution; double-buffered cp.async)
    pdl_launch(k_conv2, dim3(B / 2), dim3(256), (size_t)CV2_SMEM_BYTES);
    pdl_launch(k_bnfin2, dim3(C2), dim3(32), 0, bn2_g, bn2_b);   // gates cascade

    // stage 3 (fc1: 32-row b-tiles, grid 16x8; fc2 weight load overlaps fc1)
    pdl_launch(k_fc1, dim3(16, 8), dim3(256), 0);
    pdl_launch(k_fc2, dim3(B / 8), dim3(512), 0, fc2_b, bn3_g, bn3_b, out);
}